// round 14
// baseline (speedup 1.0000x reference)
#include <cuda_runtime.h>
#include <cstdint>
#include <math_constants.h>

#define COLS   24576
#define V4     (COLS / 4)      // 6144 float4 per row
#define NBINS  8192            // top-13 bits of monotonic key
#define NT     512             // threads per CTA
#define BPT    (NBINS / NT)    // 16 bins per thread
#define NW     (NT / 32)       // 16 warps
#define CAP    2048            // candidate buffer capacity (~560 expected per row)
#define FILT   2.0f            // collection threshold (fast path valid iff nHigh >= k)

// Order-preserving float->uint key: larger float => larger key.
__device__ __forceinline__ uint32_t fkey(float f) {
    uint32_t u = __float_as_uint(f);
    return u ^ (uint32_t)(((int32_t)u >> 31) | (int32_t)0x80000000);
}
// Inverse of fkey.
__device__ __forceinline__ float fkey_inv(uint32_t key) {
    uint32_t u = key ^ ((key & 0x80000000u) ? 0x80000000u : 0xFFFFFFFFu);
    return __uint_as_float(u);
}

__global__ __launch_bounds__(NT, 4) void topk_select_kernel(
    const float* __restrict__ z,
    const int*   __restrict__ kin,
    float*       __restrict__ out)
{
    __shared__ uint32_t hist[NBINS];       // 32 KB
    __shared__ uint32_t candKey[CAP];      // 8 KB
    __shared__ uint16_t candIdx[CAP];      // 4 KB
    __shared__ uint32_t warpTot[NW];
    __shared__ uint32_t s_binB, s_above, s_cnt, s_cnt2;

    const int tid  = threadIdx.x;
    const int lane = tid & 31;
    const int wid  = tid >> 5;
    const int row  = blockIdx.x;
    const uint32_t k = (uint32_t)(kin ? *kin : 64);

    const float4* zr   = reinterpret_cast<const float4*>(z) + (size_t)row * V4;
    float*        orow = out + (size_t)row * COLS;

    for (int i = tid; i < NBINS; i += NT) hist[i] = 0;
    if (tid == 0) { s_cnt = 0; s_cnt2 = 0; }
    __syncthreads();

    // ---- Single streaming pass (HBM read, MLP=3): histogram + collect v >= FILT ----
    #pragma unroll 1
    for (int i = tid; i < V4; i += 3 * NT) {        // V4 = 4 * (3*NT): exact
        float4 a = __ldcg(&zr[i]);
        float4 b = __ldcg(&zr[i + NT]);
        float4 c = __ldcg(&zr[i + 2 * NT]);
        const float* va = &a.x; const int ia = 4 * i;
        const float* vb = &b.x; const int ib = 4 * (i + NT);
        const float* vc = &c.x; const int ic = 4 * (i + 2 * NT);
        #pragma unroll
        for (int q = 0; q < 4; q++) {
            float v = va[q];
            if (v >= FILT) {
                uint32_t ky = fkey(v);
                atomicAdd(&hist[ky >> 19], 1u);     // unconditional: hist always complete for highs
                uint32_t p = atomicAdd(&s_cnt, 1u);
                if (p < CAP) { candKey[p] = ky; candIdx[p] = (uint16_t)(ia + q); }
            }
        }
        #pragma unroll
        for (int q = 0; q < 4; q++) {
            float v = vb[q];
            if (v >= FILT) {
                uint32_t ky = fkey(v);
                atomicAdd(&hist[ky >> 19], 1u);
                uint32_t p = atomicAdd(&s_cnt, 1u);
                if (p < CAP) { candKey[p] = ky; candIdx[p] = (uint16_t)(ib + q); }
            }
        }
        #pragma unroll
        for (int q = 0; q < 4; q++) {
            float v = vc[q];
            if (v >= FILT) {
                uint32_t ky = fkey(v);
                atomicAdd(&hist[ky >> 19], 1u);
                uint32_t p = atomicAdd(&s_cnt, 1u);
                if (p < CAP) { candKey[p] = ky; candIdx[p] = (uint16_t)(ic + q); }
            }
        }
    }
    __syncthreads();
    const uint32_t nHigh = s_cnt;
    const bool fast = (nHigh >= k) && (nHigh <= CAP);

    // ---- Slow path (generic correctness; never taken on this data): full histogram ----
    if (!fast) {
        #pragma unroll 1
        for (int i = tid; i < V4; i += NT) {
            float4 v = __ldcg(&zr[i]);
            if (!(v.x >= FILT)) atomicAdd(&hist[fkey(v.x) >> 19], 1u);
            if (!(v.y >= FILT)) atomicAdd(&hist[fkey(v.y) >> 19], 1u);
            if (!(v.z >= FILT)) atomicAdd(&hist[fkey(v.z) >> 19], 1u);
            if (!(v.w >= FILT)) atomicAdd(&hist[fkey(v.w) >> 19], 1u);
        }
        __syncthreads();
    }

    // ---- Warp-shuffle suffix scan to locate the rank-k bin ----
    const int base = tid * BPT;
    uint32_t s = 0;
    #pragma unroll
    for (int j = 0; j < BPT; j++) s += hist[base + j];
    uint32_t inc = s;                               // inclusive suffix within warp
    #pragma unroll
    for (int off = 1; off < 32; off <<= 1) {
        uint32_t o = __shfl_down_sync(0xFFFFFFFFu, inc, off);
        if (lane + off < 32) inc += o;
    }
    if (lane == 0) warpTot[wid] = inc;              // warp total
    __syncthreads();
    uint32_t ws = 0;
    #pragma unroll
    for (int w = 0; w < NW; w++) if (w > wid) ws += warpTot[w];
    uint32_t abv  = ws + (inc - s);                 // strictly above this thread's bins
    uint32_t incl = ws + inc;
    if (abv < k && incl >= k) {                     // exactly one thread matches
        uint32_t a = abv;
        #pragma unroll
        for (int j = BPT - 1; j >= 0; j--) {
            uint32_t c = hist[base + j];
            if (a + c >= k) { s_binB = (uint32_t)(base + j); s_above = a; break; }
            a += c;
        }
    }
    __syncthreads();
    const uint32_t binB = s_binB;
    const uint32_t need = k - s_above;              // winners inside threshold bin

    if (fast) {
        // ---- Fast epilogue: winners come straight from the smem candidate set ----
        // (output is already zero-filled by the preceding memset node)
        const uint32_t n = nHigh;
        for (uint32_t j = tid; j < n; j += NT) {
            uint32_t kj = candKey[j];
            uint32_t bj = kj >> 19;
            uint32_t ij = candIdx[j];
            if (bj > binB) {
                orow[ij] = fkey_inv(kj);            // definite winner
            } else if (bj == binB) {
                uint32_t r = 0;
                for (uint32_t m = 0; m < n; m++) {
                    uint32_t km = candKey[m];
                    if ((km >> 19) == binB)
                        r += (km > kj) || (km == kj && candIdx[m] < ij);
                }
                if (r < need) orow[ij] = fkey_inv(kj);
            }
        }
    } else {
        // ---- Slow epilogue: third read pass, write winners + collect tie-bin ----
        const float hiThr = (binB == NBINS - 1u) ? CUDART_INF_F : fkey_inv((binB + 1u) << 19);
        const float loThr = fkey_inv(binB << 19);
        #pragma unroll 1
        for (int i = tid; i < V4; i += NT) {
            float4 v = __ldcg(&zr[i]);
            const float* vv = &v.x;
            #pragma unroll
            for (int q = 0; q < 4; q++) {
                float x = vv[q];
                int idx = 4 * i + q;
                if (x >= hiThr) {
                    orow[idx] = x;
                } else if (x >= loThr) {
                    uint32_t p = atomicAdd(&s_cnt2, 1u);
                    if (p < CAP) { candKey[p] = fkey(x); candIdx[p] = (uint16_t)idx; }
                }
            }
        }
        __syncthreads();
        const uint32_t n = min(s_cnt2, (uint32_t)CAP);
        for (uint32_t j = tid; j < n; j += NT) {
            uint32_t kj = candKey[j];
            uint32_t ij = candIdx[j];
            uint32_t r = 0;
            for (uint32_t m = 0; m < n; m++) {
                uint32_t km = candKey[m];
                r += (km > kj) || (km == kj && candIdx[m] < ij);
            }
            if (r < need) orow[ij] = fkey_inv(kj);
        }
    }
}

extern "C" void kernel_launch(void* const* d_in, const int* in_sizes, int n_in,
                              void* d_out, int out_size) {
    const float* z   = (const float*)d_in[0];
    const int*   kin = (n_in >= 2) ? (const int*)d_in[1] : nullptr;
    float*       out = (float*)d_out;
    int rows = in_sizes[0] / COLS;   // 8192
    // Zero-fill output as a pure streaming write (graph memset node),
    // then one pure-read select kernel scatters the k winners per row.
    cudaMemsetAsync(d_out, 0, (size_t)out_size * sizeof(float));
    topk_select_kernel<<<rows, NT>>>(z, kin, out);
}

// round 16
// speedup vs baseline: 1.0050x; 1.0050x over previous
#include <cuda_runtime.h>
#include <cstdint>
#include <math_constants.h>

#define COLS   24576
#define V4     (COLS / 4)      // 6144 float4 per row
#define NBINS  8192            // top-13 bits of monotonic key
#define NT     512             // threads per CTA
#define BPT    (NBINS / NT)    // 16 bins per thread
#define NW     (NT / 32)       // 16 warps
#define CAP    2048            // candidate buffer capacity (~560 expected per row)
#define FILT   2.0f            // collection threshold (fast path valid iff nHigh >= k)

// Order-preserving float->uint key: larger float => larger key.
__device__ __forceinline__ uint32_t fkey(float f) {
    uint32_t u = __float_as_uint(f);
    return u ^ (uint32_t)(((int32_t)u >> 31) | (int32_t)0x80000000);
}
// Inverse of fkey.
__device__ __forceinline__ float fkey_inv(uint32_t key) {
    uint32_t u = key ^ ((key & 0x80000000u) ? 0x80000000u : 0xFFFFFFFFu);
    return __uint_as_float(u);
}

// Explicit-component collect: NO pointer indexing into float4 (locals spill!).
#define COLLECT(v, idx)                                                        \
    if ((v) >= FILT) {                                                         \
        uint32_t ky = fkey(v);                                                 \
        atomicAdd(&hist[ky >> 19], 1u);                                        \
        uint32_t p = atomicAdd(&s_cnt, 1u);                                    \
        if (p < CAP) { candKey[p] = ky; candIdx[p] = (uint16_t)(idx); }        \
    }

__global__ __launch_bounds__(NT, 4) void topk_select_kernel(
    const float* __restrict__ z,
    const int*   __restrict__ kin,
    float*       __restrict__ out)
{
    __shared__ uint32_t hist[NBINS];       // 32 KB
    __shared__ uint32_t candKey[CAP];      // 8 KB
    __shared__ uint16_t candIdx[CAP];      // 4 KB
    __shared__ uint32_t warpTot[NW];
    __shared__ uint32_t s_binB, s_above, s_cnt, s_cnt2;

    const int tid  = threadIdx.x;
    const int lane = tid & 31;
    const int wid  = tid >> 5;
    const int row  = blockIdx.x;
    const uint32_t k = (uint32_t)(kin ? *kin : 64);

    const float4* zr   = reinterpret_cast<const float4*>(z) + (size_t)row * V4;
    float*        orow = out + (size_t)row * COLS;

    for (int i = tid; i < NBINS; i += NT) hist[i] = 0;
    if (tid == 0) { s_cnt = 0; s_cnt2 = 0; }
    __syncthreads();

    // ---- Single streaming pass (HBM read, MLP=3): histogram + collect v >= FILT ----
    #pragma unroll 1
    for (int i = tid; i < V4; i += 3 * NT) {        // V4 = 4 * (3*NT): exact
        float4 a = __ldcg(&zr[i]);
        float4 b = __ldcg(&zr[i + NT]);
        float4 c = __ldcg(&zr[i + 2 * NT]);
        const int ia = 4 * i;
        const int ib = 4 * (i + NT);
        const int ic = 4 * (i + 2 * NT);
        COLLECT(a.x, ia + 0) COLLECT(a.y, ia + 1) COLLECT(a.z, ia + 2) COLLECT(a.w, ia + 3)
        COLLECT(b.x, ib + 0) COLLECT(b.y, ib + 1) COLLECT(b.z, ib + 2) COLLECT(b.w, ib + 3)
        COLLECT(c.x, ic + 0) COLLECT(c.y, ic + 1) COLLECT(c.z, ic + 2) COLLECT(c.w, ic + 3)
    }
    __syncthreads();
    const uint32_t nHigh = s_cnt;
    const bool fast = (nHigh >= k) && (nHigh <= CAP);

    // ---- Slow path (generic correctness; never taken on this data): full histogram ----
    if (!fast) {
        #pragma unroll 1
        for (int i = tid; i < V4; i += NT) {
            float4 v = __ldcg(&zr[i]);
            if (!(v.x >= FILT)) atomicAdd(&hist[fkey(v.x) >> 19], 1u);
            if (!(v.y >= FILT)) atomicAdd(&hist[fkey(v.y) >> 19], 1u);
            if (!(v.z >= FILT)) atomicAdd(&hist[fkey(v.z) >> 19], 1u);
            if (!(v.w >= FILT)) atomicAdd(&hist[fkey(v.w) >> 19], 1u);
        }
        __syncthreads();
    }

    // ---- Warp-shuffle suffix scan to locate the rank-k bin ----
    const int base = tid * BPT;
    uint32_t s = 0;
    #pragma unroll
    for (int j = 0; j < BPT; j++) s += hist[base + j];
    uint32_t inc = s;                               // inclusive suffix within warp
    #pragma unroll
    for (int off = 1; off < 32; off <<= 1) {
        uint32_t o = __shfl_down_sync(0xFFFFFFFFu, inc, off);
        if (lane + off < 32) inc += o;
    }
    if (lane == 0) warpTot[wid] = inc;              // warp total
    __syncthreads();
    uint32_t ws = 0;
    #pragma unroll
    for (int w = 0; w < NW; w++) if (w > wid) ws += warpTot[w];
    uint32_t abv  = ws + (inc - s);                 // strictly above this thread's bins
    uint32_t incl = ws + inc;
    if (abv < k && incl >= k) {                     // exactly one thread matches
        uint32_t a = abv;
        #pragma unroll
        for (int j = BPT - 1; j >= 0; j--) {
            uint32_t c = hist[base + j];
            if (a + c >= k) { s_binB = (uint32_t)(base + j); s_above = a; break; }
            a += c;
        }
    }
    __syncthreads();
    const uint32_t binB = s_binB;
    const uint32_t need = k - s_above;              // winners inside threshold bin

    if (fast) {
        // ---- Fast epilogue: winners come straight from the smem candidate set ----
        // (output already zero-filled by the preceding memset node)
        const uint32_t n = nHigh;
        for (uint32_t j = tid; j < n; j += NT) {
            uint32_t kj = candKey[j];
            uint32_t bj = kj >> 19;
            uint32_t ij = candIdx[j];
            if (bj > binB) {
                orow[ij] = fkey_inv(kj);            // definite winner
            } else if (bj == binB) {
                uint32_t r = 0;
                for (uint32_t m = 0; m < n; m++) {
                    uint32_t km = candKey[m];
                    if ((km >> 19) == binB)
                        r += (km > kj) || (km == kj && candIdx[m] < ij);
                }
                if (r < need) orow[ij] = fkey_inv(kj);
            }
        }
    } else {
        // ---- Slow epilogue: third read pass, write winners + collect tie-bin ----
        const float hiThr = (binB == NBINS - 1u) ? CUDART_INF_F : fkey_inv((binB + 1u) << 19);
        const float loThr = fkey_inv(binB << 19);
        #pragma unroll 1
        for (int i = tid; i < V4; i += NT) {
            float4 v = __ldcg(&zr[i]);
            int idx = 4 * i;
            if (v.x >= hiThr) orow[idx + 0] = v.x;
            else if (v.x >= loThr) { uint32_t p = atomicAdd(&s_cnt2, 1u); if (p < CAP) { candKey[p] = fkey(v.x); candIdx[p] = (uint16_t)(idx + 0); } }
            if (v.y >= hiThr) orow[idx + 1] = v.y;
            else if (v.y >= loThr) { uint32_t p = atomicAdd(&s_cnt2, 1u); if (p < CAP) { candKey[p] = fkey(v.y); candIdx[p] = (uint16_t)(idx + 1); } }
            if (v.z >= hiThr) orow[idx + 2] = v.z;
            else if (v.z >= loThr) { uint32_t p = atomicAdd(&s_cnt2, 1u); if (p < CAP) { candKey[p] = fkey(v.z); candIdx[p] = (uint16_t)(idx + 2); } }
            if (v.w >= hiThr) orow[idx + 3] = v.w;
            else if (v.w >= loThr) { uint32_t p = atomicAdd(&s_cnt2, 1u); if (p < CAP) { candKey[p] = fkey(v.w); candIdx[p] = (uint16_t)(idx + 3); } }
        }
        __syncthreads();
        const uint32_t n = min(s_cnt2, (uint32_t)CAP);
        for (uint32_t j = tid; j < n; j += NT) {
            uint32_t kj = candKey[j];
            uint32_t ij = candIdx[j];
            uint32_t r = 0;
            for (uint32_t m = 0; m < n; m++) {
                uint32_t km = candKey[m];
                r += (km > kj) || (km == kj && candIdx[m] < ij);
            }
            if (r < need) orow[ij] = fkey_inv(kj);
        }
    }
}

extern "C" void kernel_launch(void* const* d_in, const int* in_sizes, int n_in,
                              void* d_out, int out_size) {
    const float* z   = (const float*)d_in[0];
    const int*   kin = (n_in >= 2) ? (const int*)d_in[1] : nullptr;
    float*       out = (float*)d_out;
    int rows = in_sizes[0] / COLS;   // 8192
    // Zero-fill output as a pure streaming write (graph memset node),
    // then one pure-read select kernel scatters the k winners per row.
    cudaMemsetAsync(d_out, 0, (size_t)out_size * sizeof(float));
    topk_select_kernel<<<rows, NT>>>(z, kin, out);
}